// round 3
// baseline (speedup 1.0000x reference)
#include <cuda_runtime.h>

// Problem constants (fixed by setup_inputs): B=4, C=128, W=H=64
#define NB  4
#define NCH 64      // c_half = c_out
#define ND  8       // d_qk
#define NN  4096    // W*H tokens
#define MT  32      // query tile (rows per block)  -> grid 512
#define NT  64      // key tile
#define VPAD 68     // padded smem row stride for v (floats)
#define WPAD 36     // padded smem row stride for w (floats), 16B-aligned

typedef unsigned long long ull;

// Scratch (no cudaMalloc allowed) — 16B aligned for vector access.
__device__ __align__(16) float g_p2t[NB * NN * ND];    // [b][n][8]
__device__ __align__(16) float g_p3t[NB * NN * ND];    // [b][n][8]
__device__ __align__(16) float g_v3t[NB * NN * NCH];   // [b][n][64]

// ---- packed fp32x2 helpers (ptxas will not auto-fuse; PTX only) ----
__device__ __forceinline__ ull f2fma(ull a, ull b, ull c) {
    ull d; asm("fma.rn.f32x2 %0, %1, %2, %3;" : "=l"(d) : "l"(a), "l"(b), "l"(c)); return d;
}
__device__ __forceinline__ ull f2mul(ull a, ull b) {
    ull d; asm("mul.rn.f32x2 %0, %1, %2;" : "=l"(d) : "l"(a), "l"(b)); return d;
}
__device__ __forceinline__ ull fpack(float x) {
    ull d; asm("mov.b64 %0, {%1, %1};" : "=l"(d) : "f"(x)); return d;
}
__device__ __forceinline__ float2 funpack(ull a) {
    float2 r; asm("mov.b64 {%0, %1}, %2;" : "=f"(r.x), "=f"(r.y) : "l"(a)); return r;
}

// dot of 8-float q (pre-packed as 4 x f32x2) with 8-float key (16B-aligned smem)
__device__ __forceinline__ float dotp8(const ull* q, const float* key) {
    const ulonglong2 k0 = ((const ulonglong2*)key)[0];
    const ulonglong2 k1 = ((const ulonglong2*)key)[1];
    ull a = f2mul(q[0], k0.x);
    a = f2fma(q[1], k0.y, a);
    a = f2fma(q[2], k1.x, a);
    a = f2fma(q[3], k1.y, a);
    float2 f = funpack(a);
    return f.x + f.y;
}

// ---------------------------------------------------------------------------
// K1: 1x1-conv projections, written n-major.
// ---------------------------------------------------------------------------
__global__ void proj_kernel(const float* __restrict__ x,
                            const float* __restrict__ wq2, const float* __restrict__ bq2,
                            const float* __restrict__ wq3, const float* __restrict__ bq3,
                            const float* __restrict__ wv3, const float* __restrict__ bv3)
{
    __shared__ float s_wq2[ND * NCH];
    __shared__ float s_wq3[ND * NCH];
    __shared__ float s_wv3[NCH * NCH];
    __shared__ float s_b[2 * ND + NCH];

    const int tid = threadIdx.x;
    for (int i = tid; i < ND * NCH; i += 256) { s_wq2[i] = wq2[i]; s_wq3[i] = wq3[i]; }
    for (int i = tid; i < NCH * NCH; i += 256) s_wv3[i] = wv3[i];
    if (tid < ND)                s_b[tid] = bq2[tid];
    else if (tid < 2 * ND)       s_b[tid] = bq3[tid - ND];
    else if (tid < 2 * ND + NCH) s_b[tid] = bv3[tid - 2 * ND];
    __syncthreads();

    const int b = blockIdx.y;
    const int n = blockIdx.x * 256 + tid;
    const float* xb = x + (size_t)b * (2 * NCH) * NN;

    float p2[ND], p3[ND], v[NCH];
#pragma unroll
    for (int d = 0; d < ND; d++) { p2[d] = s_b[d]; p3[d] = s_b[ND + d]; }
#pragma unroll
    for (int c = 0; c < NCH; c++) v[c] = s_b[2 * ND + c];

    for (int c = 0; c < NCH; c++) {
        const float x3v = xb[c * NN + n];
        const float x2v = xb[(NCH + c) * NN + n];
#pragma unroll
        for (int d = 0; d < ND; d++) {
            p2[d] = fmaf(s_wq2[d * NCH + c], x2v, p2[d]);
            p3[d] = fmaf(s_wq3[d * NCH + c], x3v, p3[d]);
        }
#pragma unroll
        for (int o = 0; o < NCH; o++)
            v[o] = fmaf(s_wv3[o * NCH + c], x3v, v[o]);
    }

    float* o2 = g_p2t + ((size_t)b * NN + n) * ND;
    float* o3 = g_p3t + ((size_t)b * NN + n) * ND;
    float* ov = g_v3t + ((size_t)b * NN + n) * NCH;
#pragma unroll
    for (int d = 0; d < ND; d++) { o2[d] = p2[d]; o3[d] = p3[d]; }
#pragma unroll
    for (int c = 0; c < NCH; c++) ov[c] = v[c];
}

// ---------------------------------------------------------------------------
// K2: two-phase attention per (batch, 32-query tile). 256 threads.
//  Thread roles:
//    score/softmax phases: (m = tid>>3) in 0..31, (part = tid&7) -> 8 keys/tile
//    GEMM: half = tid>>7 handles n-half of tile; within half:
//          mg = t&7 (4 m's), cg = t>>3 (4 c's); 4x4 register tile via f32x2.
// ---------------------------------------------------------------------------
__global__ __launch_bounds__(256, 3) void att_kernel(const float* __restrict__ x,
                                                     const float* __restrict__ g2p,
                                                     const float* __restrict__ g3p,
                                                     float* __restrict__ out)
{
    __shared__ __align__(16) float s_p2[NT * ND];        // [n][8]
    __shared__ __align__(16) float s_p3[NT * ND];
    __shared__ __align__(16) float s_v[NT][VPAD];        // [n][c]
    __shared__ __align__(16) float s_w[NT][WPAD];        // [n][m swizzled]
    __shared__ float s_sc32[MT], s_sc33[MT];

    const int tid  = threadIdx.x;
    const int b    = blockIdx.y;
    const int m0   = blockIdx.x * MT;
    const int m    = tid >> 3;               // 0..31 query row
    const int part = tid & 7;                // 8 threads per row

    const float g2 = *g2p;
    const float g3 = *g3p;

    const float4* p2g = (const float4*)g_p2t + (size_t)b * NN * 2;
    const float4* p3g = (const float4*)g_p3t + (size_t)b * NN * 2;

    // this thread's p3 query row, packed as 4 x f32x2
    ull q[4];
    {
        const ulonglong2 qa = ((const ulonglong2*)p3g)[(m0 + m) * 2 + 0];
        const ulonglong2 qb = ((const ulonglong2*)p3g)[(m0 + m) * 2 + 1];
        q[0] = qa.x; q[1] = qa.y; q[2] = qb.x; q[3] = qb.y;
    }

    // ---------------- Phase 1: softmax denominators (max-free, logits small) ---
    float sum32 = 0.f, sum33 = 0.f;
    float4 pr = (tid < 128) ? p2g[tid] : p3g[tid - 128];
    for (int t = 0; t < NN / NT; t++) {
        __syncthreads();
        if (tid < 128) ((float4*)s_p2)[tid]       = pr;
        else           ((float4*)s_p3)[tid - 128] = pr;
        __syncthreads();
        if (t + 1 < NN / NT) {
            const int base = (t + 1) * NT * 2;
            pr = (tid < 128) ? p2g[base + tid] : p3g[base + tid - 128];
        }
#pragma unroll
        for (int i = 0; i < 8; i++) {
            const int n = part * 8 + i;
            const float s32 = dotp8(q, s_p2 + n * ND);
            const float s33 = dotp8(q, s_p3 + n * ND);
            sum32 += __expf(s32);
            sum33 += __expf(s33);
        }
    }
    sum32 += __shfl_xor_sync(0xffffffffu, sum32, 1);
    sum32 += __shfl_xor_sync(0xffffffffu, sum32, 2);
    sum32 += __shfl_xor_sync(0xffffffffu, sum32, 4);
    sum33 += __shfl_xor_sync(0xffffffffu, sum33, 1);
    sum33 += __shfl_xor_sync(0xffffffffu, sum33, 2);
    sum33 += __shfl_xor_sync(0xffffffffu, sum33, 4);
    if (part == 0) { s_sc32[m] = g2 / sum32; s_sc33[m] = g3 / sum33; }
    __syncthreads();
    const float sc32 = s_sc32[m];
    const float sc33 = s_sc33[m];
    // swizzled column base for this thread's weight writes
    const int wcol = (((m >> 2) ^ part) << 2) | (m & 3);

    // ---------------- Phase 2: combined-weight GEMM ----------------
    const int half = tid >> 7;               // n-half of each 64-key tile
    const int t7   = tid & 127;
    const int mg   = t7 & 7;                 // m-group (4 m's)
    const int cg   = t7 >> 3;                // c-group (4 c's)
    const int nlo  = half * 32;

    ull acc[2][4];                           // [m-pair][c], each ull = 2 m's
#pragma unroll
    for (int i = 0; i < 2; i++)
#pragma unroll
        for (int j = 0; j < 4; j++) acc[i][j] = 0ull;

    const float4* vg = (const float4*)g_v3t + (size_t)b * NN * (NCH / 4);

    // prefetch tile 0
    pr = (tid < 128) ? p2g[tid] : p3g[tid - 128];
    float4 vr[4];
#pragma unroll
    for (int k = 0; k < 4; k++) vr[k] = vg[tid + k * 256];

    for (int t = 0; t < NN / NT; t++) {
        __syncthreads();
        if (tid < 128) ((float4*)s_p2)[tid]       = pr;
        else           ((float4*)s_p3)[tid - 128] = pr;
#pragma unroll
        for (int k = 0; k < 4; k++) {
            const int fi = tid + k * 256;
            ((float4*)&s_v[fi >> 4][0])[fi & 15] = vr[k];
        }
        __syncthreads();
        if (t + 1 < NN / NT) {
            const int base = (t + 1) * NT * 2;
            pr = (tid < 128) ? p2g[base + tid] : p3g[base + tid - 128];
#pragma unroll
            for (int k = 0; k < 4; k++) vr[k] = vg[(t + 1) * NT * (NCH / 4) + tid + k * 256];
        }

        // weight generation: each (m,n) once; conflict-free swizzled STS
#pragma unroll
        for (int i = 0; i < 8; i++) {
            const int n = part * 8 + i;
            const float s32 = dotp8(q, s_p2 + n * ND);
            const float s33 = dotp8(q, s_p3 + n * ND);
            s_w[n][wcol] = fmaf(sc32, __expf(s32), sc33 * __expf(s33));
        }
        __syncthreads();

        // GEMM over this thread's n-half: acc[mpair][c] += w[n][m] * v[n][c]
#pragma unroll 8
        for (int nn = 0; nn < 32; nn++) {
            const int n  = nlo + nn;
            const int sw = (n >> 3) & 7;
            const ulonglong2 w2 = *(const ulonglong2*)(&s_w[n][(mg ^ sw) << 2]);
            const float4 vv = *(const float4*)(&s_v[n][cg << 2]);
            const ull vb0 = fpack(vv.x), vb1 = fpack(vv.y);
            const ull vb2 = fpack(vv.z), vb3 = fpack(vv.w);
            acc[0][0] = f2fma(w2.x, vb0, acc[0][0]);
            acc[0][1] = f2fma(w2.x, vb1, acc[0][1]);
            acc[0][2] = f2fma(w2.x, vb2, acc[0][2]);
            acc[0][3] = f2fma(w2.x, vb3, acc[0][3]);
            acc[1][0] = f2fma(w2.y, vb0, acc[1][0]);
            acc[1][1] = f2fma(w2.y, vb1, acc[1][1]);
            acc[1][2] = f2fma(w2.y, vb2, acc[1][2]);
            acc[1][3] = f2fma(w2.y, vb3, acc[1][3]);
        }
    }

    // ---------------- cross-half reduction + epilogue ----------------
    float* s_red = &s_v[0][0];               // reuse: [32][65]
    __syncthreads();
    if (half == 1) {
#pragma unroll
        for (int p = 0; p < 2; p++)
#pragma unroll
            for (int j = 0; j < 4; j++) {
                const float2 f = funpack(acc[p][j]);
                const int ml = mg * 4 + p * 2;
                const int c  = cg * 4 + j;
                s_red[ml * 65 + c]       = f.x;
                s_red[(ml + 1) * 65 + c] = f.y;
            }
    }
    __syncthreads();
    if (half == 0) {
        const float* xb = x + (size_t)b * (2 * NCH) * NN;  // x3 = channels 0..63
        float* ob = out + (size_t)b * NCH * NN;
        const int mm = m0 + mg * 4;
#pragma unroll
        for (int j = 0; j < 4; j++) {
            const int c = cg * 4 + j;
            const float2 a0 = funpack(acc[0][j]);
            const float2 a1 = funpack(acc[1][j]);
            const float4 xv = *(const float4*)(xb + (size_t)c * NN + mm);
            float4 o;
            o.x = a0.x + s_red[(mg * 4 + 0) * 65 + c] + xv.x;
            o.y = a0.y + s_red[(mg * 4 + 1) * 65 + c] + xv.y;
            o.z = a1.x + s_red[(mg * 4 + 2) * 65 + c] + xv.z;
            o.w = a1.y + s_red[(mg * 4 + 3) * 65 + c] + xv.w;
            *(float4*)(ob + (size_t)c * NN + mm) = o;
        }
    }
}

extern "C" void kernel_launch(void* const* d_in, const int* in_sizes, int n_in,
                              void* d_out, int out_size)
{
    const float* x   = (const float*)d_in[0];
    const float* wq2 = (const float*)d_in[1];
    const float* bq2 = (const float*)d_in[2];
    const float* wq3 = (const float*)d_in[3];
    const float* bq3 = (const float*)d_in[4];
    const float* wv3 = (const float*)d_in[5];
    const float* bv3 = (const float*)d_in[6];
    const float* g2  = (const float*)d_in[7];
    const float* g3  = (const float*)d_in[8];
    float* out = (float*)d_out;

    proj_kernel<<<dim3(NN / 256, NB), 256>>>(x, wq2, bq2, wq3, bq3, wv3, bv3);
    att_kernel<<<dim3(NN / MT, NB), 256>>>(x, g2, g3, out);
}

// round 4
// speedup vs baseline: 3.0871x; 3.0871x over previous
#include <cuda_runtime.h>

// Problem constants (fixed by setup_inputs): B=4, C=128, W=H=64
#define NB  4
#define NCH 64      // c_half = c_out
#define ND  8       // d_qk
#define NN  4096    // W*H tokens
#define MT  64      // query tile (rows per block)  -> grid 256
#define NT  64      // key tile
#define VPAD 68     // padded smem row stride for v (floats)
#define WPAD 68     // padded smem row stride for w (floats)

// Scratch (no cudaMalloc allowed) — 16B aligned for vector access.
__device__ __align__(16) float g_p2t[NB * NN * ND];    // [b][n][8]
__device__ __align__(16) float g_p3t[NB * NN * ND];    // [b][n][8]
__device__ __align__(16) float g_v3t[NB * NN * NCH];   // [b][n][64]

// ---------------------------------------------------------------------------
// K1: 1x1-conv projections, written n-major.
// ---------------------------------------------------------------------------
__global__ void proj_kernel(const float* __restrict__ x,
                            const float* __restrict__ wq2, const float* __restrict__ bq2,
                            const float* __restrict__ wq3, const float* __restrict__ bq3,
                            const float* __restrict__ wv3, const float* __restrict__ bv3)
{
    __shared__ float s_wq2[ND * NCH];
    __shared__ float s_wq3[ND * NCH];
    __shared__ float s_wv3[NCH * NCH];
    __shared__ float s_b[2 * ND + NCH];

    const int tid = threadIdx.x;
    for (int i = tid; i < ND * NCH; i += 256) { s_wq2[i] = wq2[i]; s_wq3[i] = wq3[i]; }
    for (int i = tid; i < NCH * NCH; i += 256) s_wv3[i] = wv3[i];
    if (tid < ND)                s_b[tid] = bq2[tid];
    else if (tid < 2 * ND)       s_b[tid] = bq3[tid - ND];
    else if (tid < 2 * ND + NCH) s_b[tid] = bv3[tid - 2 * ND];
    __syncthreads();

    const int b = blockIdx.y;
    const int n = blockIdx.x * 256 + tid;
    const float* xb = x + (size_t)b * (2 * NCH) * NN;

    float p2[ND], p3[ND], v[NCH];
#pragma unroll
    for (int d = 0; d < ND; d++) { p2[d] = s_b[d]; p3[d] = s_b[ND + d]; }
#pragma unroll
    for (int c = 0; c < NCH; c++) v[c] = s_b[2 * ND + c];

    for (int c = 0; c < NCH; c++) {
        const float x3v = xb[c * NN + n];
        const float x2v = xb[(NCH + c) * NN + n];
#pragma unroll
        for (int d = 0; d < ND; d++) {
            p2[d] = fmaf(s_wq2[d * NCH + c], x2v, p2[d]);
            p3[d] = fmaf(s_wq3[d * NCH + c], x3v, p3[d]);
        }
#pragma unroll
        for (int o = 0; o < NCH; o++)
            v[o] = fmaf(s_wv3[o * NCH + c], x3v, v[o]);
    }

    float* o2 = g_p2t + ((size_t)b * NN + n) * ND;
    float* o3 = g_p3t + ((size_t)b * NN + n) * ND;
    float* ov = g_v3t + ((size_t)b * NN + n) * NCH;
#pragma unroll
    for (int d = 0; d < ND; d++) { o2[d] = p2[d]; o3[d] = p3[d]; }
#pragma unroll
    for (int c = 0; c < NCH; c++) ov[c] = v[c];
}

__device__ __forceinline__ float dot8(const float4 a, const float4 b,
                                      const float4 c, const float4 d)
{
    float s = a.x * c.x;
    s = fmaf(a.y, c.y, s);
    s = fmaf(a.z, c.z, s);
    s = fmaf(a.w, c.w, s);
    s = fmaf(b.x, d.x, s);
    s = fmaf(b.y, d.y, s);
    s = fmaf(b.z, d.z, s);
    s = fmaf(b.w, d.w, s);
    return s;
}

// ---------------------------------------------------------------------------
// K2: two-phase attention per (batch, 64-query tile). 256 threads.
//  Score/weight phases: thread owns 4 consecutive query rows
//      mq = tid & 15  -> m = mq*4 + {0..3};  np = tid >> 4 -> n = np*4 + {0..3}
//      (4 m's amortize each 32B key read over 64 FMA lanes)
//  GEMM: K-split in 2 halves of the key tile; within half (128 thr):
//      mg = t&7 (8 m's = mg*8..), cg = t>>3 (4 c's = cg*4..); 8x4 fp32 tile.
// ---------------------------------------------------------------------------
__global__ __launch_bounds__(256, 2) void att_kernel(const float* __restrict__ x,
                                                     const float* __restrict__ g2p,
                                                     const float* __restrict__ g3p,
                                                     float* __restrict__ out)
{
    __shared__ __align__(16) float s_p2[NT * ND];        // [n][8]
    __shared__ __align__(16) float s_p3[NT * ND];
    __shared__ __align__(16) float s_v[NT][VPAD];        // [n][c]
    __shared__ __align__(16) float s_w[NT][WPAD];        // [n][m]
    __shared__ float s_sc32[MT], s_sc33[MT];

    const int tid = threadIdx.x;
    const int b   = blockIdx.y;
    const int m0  = blockIdx.x * MT;
    const int mq  = tid & 15;                // m-group: 4 consecutive rows
    const int np  = tid >> 4;                // n-part: 4 consecutive keys/tile

    const float g2 = *g2p;
    const float g3 = *g3p;

    const float4* p2g = (const float4*)g_p2t + (size_t)b * NN * 2;
    const float4* p3g = (const float4*)g_p3t + (size_t)b * NN * 2;

    // 4 query rows (p3) in registers for the whole kernel
    float4 qa[4], qb[4];
#pragma unroll
    for (int k = 0; k < 4; k++) {
        qa[k] = p3g[(m0 + mq * 4 + k) * 2 + 0];
        qb[k] = p3g[(m0 + mq * 4 + k) * 2 + 1];
    }

    // ---------------- Phase 1: softmax denominators (max-free) ----------------
    float sum32[4] = {0.f, 0.f, 0.f, 0.f};
    float sum33[4] = {0.f, 0.f, 0.f, 0.f};
    float4 pr = (tid < 128) ? p2g[tid] : p3g[tid - 128];
    for (int t = 0; t < NN / NT; t++) {
        __syncthreads();
        if (tid < 128) ((float4*)s_p2)[tid]       = pr;
        else           ((float4*)s_p3)[tid - 128] = pr;
        __syncthreads();
        if (t + 1 < NN / NT) {
            const int base = (t + 1) * NT * 2;
            pr = (tid < 128) ? p2g[base + tid] : p3g[base + tid - 128];
        }
#pragma unroll
        for (int i = 0; i < 4; i++) {
            const int n = np * 4 + i;
            const float4 k2a = ((const float4*)s_p2)[n * 2];
            const float4 k2b = ((const float4*)s_p2)[n * 2 + 1];
            const float4 k3a = ((const float4*)s_p3)[n * 2];
            const float4 k3b = ((const float4*)s_p3)[n * 2 + 1];
#pragma unroll
            for (int k = 0; k < 4; k++) {
                sum32[k] += __expf(dot8(qa[k], qb[k], k2a, k2b));
                sum33[k] += __expf(dot8(qa[k], qb[k], k3a, k3b));
            }
        }
    }
    // pairwise reduce lanes l / l+16 (same mq, adjacent np)
#pragma unroll
    for (int k = 0; k < 4; k++) {
        sum32[k] += __shfl_xor_sync(0xffffffffu, sum32[k], 16);
        sum33[k] += __shfl_xor_sync(0xffffffffu, sum33[k], 16);
    }
    // cross-warp reduction through smem (reuse s_w region)
    {
        float* s_red = &s_w[0][0];           // [16 mq][8 warp][8 vals]
        const int warp = tid >> 5, lane = tid & 31;
        if (lane < 16) {
#pragma unroll
            for (int k = 0; k < 4; k++) {
                s_red[(lane * 8 + warp) * 8 + k]     = sum32[k];
                s_red[(lane * 8 + warp) * 8 + 4 + k] = sum33[k];
            }
        }
        __syncthreads();
        if (tid < 128) {
            const int m = tid >> 1, type = tid & 1;
            const int mq_ = m >> 2, k_ = m & 3;
            float s = 0.f;
#pragma unroll
            for (int w = 0; w < 8; w++)
                s += s_red[(mq_ * 8 + w) * 8 + type * 4 + k_];
            if (type == 0) s_sc32[m] = g2 / s;
            else           s_sc33[m] = g3 / s;
        }
        __syncthreads();
    }
    float sc32[4], sc33[4];
#pragma unroll
    for (int k = 0; k < 4; k++) { sc32[k] = s_sc32[mq * 4 + k]; sc33[k] = s_sc33[mq * 4 + k]; }

    // ---------------- Phase 2: combined-weight GEMM ----------------
    const int half = tid >> 7;               // n-half of each 64-key tile
    const int t7   = tid & 127;
    const int mg   = t7 & 7;                 // 8 m's = mg*8 .. mg*8+7
    const int cg   = t7 >> 3;                // 4 c's = cg*4 .. cg*4+3
    const int nlo  = half * 32;

    float acc[8][4];
#pragma unroll
    for (int r = 0; r < 8; r++)
#pragma unroll
        for (int j = 0; j < 4; j++) acc[r][j] = 0.f;

    const float4* vg = (const float4*)g_v3t + (size_t)b * NN * (NCH / 4);

    pr = (tid < 128) ? p2g[tid] : p3g[tid - 128];
    float4 vr[4];
#pragma unroll
    for (int k = 0; k < 4; k++) vr[k] = vg[tid + k * 256];

    for (int t = 0; t < NN / NT; t++) {
        __syncthreads();
        if (tid < 128) ((float4*)s_p2)[tid]       = pr;
        else           ((float4*)s_p3)[tid - 128] = pr;
#pragma unroll
        for (int k = 0; k < 4; k++) {
            const int fi = tid + k * 256;
            *(float4*)(&s_v[fi >> 4][(fi & 15) * 4]) = vr[k];
        }
        __syncthreads();
        if (t + 1 < NN / NT) {
            const int base = (t + 1) * NT * 2;
            pr = (tid < 128) ? p2g[base + tid] : p3g[base + tid - 128];
#pragma unroll
            for (int k = 0; k < 4; k++) vr[k] = vg[(t + 1) * NT * (NCH / 4) + tid + k * 256];
        }

        // weight generation: 4 keys x 4 query rows, one STS.128 per key
#pragma unroll
        for (int i = 0; i < 4; i++) {
            const int n = np * 4 + i;
            const float4 k2a = ((const float4*)s_p2)[n * 2];
            const float4 k2b = ((const float4*)s_p2)[n * 2 + 1];
            const float4 k3a = ((const float4*)s_p3)[n * 2];
            const float4 k3b = ((const float4*)s_p3)[n * 2 + 1];
            float4 wv;
            wv.x = fmaf(sc32[0], __expf(dot8(qa[0], qb[0], k2a, k2b)),
                        sc33[0] * __expf(dot8(qa[0], qb[0], k3a, k3b)));
            wv.y = fmaf(sc32[1], __expf(dot8(qa[1], qb[1], k2a, k2b)),
                        sc33[1] * __expf(dot8(qa[1], qb[1], k3a, k3b)));
            wv.z = fmaf(sc32[2], __expf(dot8(qa[2], qb[2], k2a, k2b)),
                        sc33[2] * __expf(dot8(qa[2], qb[2], k3a, k3b)));
            wv.w = fmaf(sc32[3], __expf(dot8(qa[3], qb[3], k2a, k2b)),
                        sc33[3] * __expf(dot8(qa[3], qb[3], k3a, k3b)));
            *(float4*)(&s_w[n][mq * 4]) = wv;
        }
        __syncthreads();

        // GEMM over this thread's n-half: acc[m][c] += w[n][m] * v[n][c]
#pragma unroll 8
        for (int nn = 0; nn < 32; nn++) {
            const int n = nlo + nn;
            const float4 w0 = *(const float4*)(&s_w[n][mg * 8]);
            const float4 w1 = *(const float4*)(&s_w[n][mg * 8 + 4]);
            const float4 vv = *(const float4*)(&s_v[n][cg * 4]);
            acc[0][0] = fmaf(w0.x, vv.x, acc[0][0]);
            acc[0][1] = fmaf(w0.x, vv.y, acc[0][1]);
            acc[0][2] = fmaf(w0.x, vv.z, acc[0][2]);
            acc[0][3] = fmaf(w0.x, vv.w, acc[0][3]);
            acc[1][0] = fmaf(w0.y, vv.x, acc[1][0]);
            acc[1][1] = fmaf(w0.y, vv.y, acc[1][1]);
            acc[1][2] = fmaf(w0.y, vv.z, acc[1][2]);
            acc[1][3] = fmaf(w0.y, vv.w, acc[1][3]);
            acc[2][0] = fmaf(w0.z, vv.x, acc[2][0]);
            acc[2][1] = fmaf(w0.z, vv.y, acc[2][1]);
            acc[2][2] = fmaf(w0.z, vv.z, acc[2][2]);
            acc[2][3] = fmaf(w0.z, vv.w, acc[2][3]);
            acc[3][0] = fmaf(w0.w, vv.x, acc[3][0]);
            acc[3][1] = fmaf(w0.w, vv.y, acc[3][1]);
            acc[3][2] = fmaf(w0.w, vv.z, acc[3][2]);
            acc[3][3] = fmaf(w0.w, vv.w, acc[3][3]);
            acc[4][0] = fmaf(w1.x, vv.x, acc[4][0]);
            acc[4][1] = fmaf(w1.x, vv.y, acc[4][1]);
            acc[4][2] = fmaf(w1.x, vv.z, acc[4][2]);
            acc[4][3] = fmaf(w1.x, vv.w, acc[4][3]);
            acc[5][0] = fmaf(w1.y, vv.x, acc[5][0]);
            acc[5][1] = fmaf(w1.y, vv.y, acc[5][1]);
            acc[5][2] = fmaf(w1.y, vv.z, acc[5][2]);
            acc[5][3] = fmaf(w1.y, vv.w, acc[5][3]);
            acc[6][0] = fmaf(w1.z, vv.x, acc[6][0]);
            acc[6][1] = fmaf(w1.z, vv.y, acc[6][1]);
            acc[6][2] = fmaf(w1.z, vv.z, acc[6][2]);
            acc[6][3] = fmaf(w1.z, vv.w, acc[6][3]);
            acc[7][0] = fmaf(w1.w, vv.x, acc[7][0]);
            acc[7][1] = fmaf(w1.w, vv.y, acc[7][1]);
            acc[7][2] = fmaf(w1.w, vv.z, acc[7][2]);
            acc[7][3] = fmaf(w1.w, vv.w, acc[7][3]);
        }
    }

    // ---------------- cross-half reduction + epilogue ----------------
    float* s_red = &s_v[0][0];               // reuse as [64 m][65]
    __syncthreads();
    if (half == 1) {
#pragma unroll
        for (int r = 0; r < 8; r++)
#pragma unroll
            for (int j = 0; j < 4; j++)
                s_red[(mg * 8 + r) * 65 + cg * 4 + j] = acc[r][j];
    }
    __syncthreads();
    if (half == 0) {
        const float* xb = x + (size_t)b * (2 * NCH) * NN;  // x3 = channels 0..63
        float* ob = out + (size_t)b * NCH * NN;
#pragma unroll
        for (int j = 0; j < 4; j++) {
            const int c = cg * 4 + j;
#pragma unroll
            for (int rb = 0; rb < 2; rb++) {
                const int mm = m0 + mg * 8 + rb * 4;
                const float4 xv = *(const float4*)(xb + (size_t)c * NN + mm);
                float4 o;
                o.x = acc[rb * 4 + 0][j] + s_red[(mg * 8 + rb * 4 + 0) * 65 + c] + xv.x;
                o.y = acc[rb * 4 + 1][j] + s_red[(mg * 8 + rb * 4 + 1) * 65 + c] + xv.y;
                o.z = acc[rb * 4 + 2][j] + s_red[(mg * 8 + rb * 4 + 2) * 65 + c] + xv.z;
                o.w = acc[rb * 4 + 3][j] + s_red[(mg * 8 + rb * 4 + 3) * 65 + c] + xv.w;
                *(float4*)(ob + (size_t)c * NN + mm) = o;
            }
        }
    }
}

extern "C" void kernel_launch(void* const* d_in, const int* in_sizes, int n_in,
                              void* d_out, int out_size)
{
    const float* x   = (const float*)d_in[0];
    const float* wq2 = (const float*)d_in[1];
    const float* bq2 = (const float*)d_in[2];
    const float* wq3 = (const float*)d_in[3];
    const float* bq3 = (const float*)d_in[4];
    const float* wv3 = (const float*)d_in[5];
    const float* bv3 = (const float*)d_in[6];
    const float* g2  = (const float*)d_in[7];
    const float* g3  = (const float*)d_in[8];
    float* out = (float*)d_out;

    proj_kernel<<<dim3(NN / 256, NB), 256>>>(x, wq2, bq2, wq3, bq3, wv3, bv3);
    att_kernel<<<dim3(NN / MT, NB), 256>>>(x, g2, g3, out);
}